// round 3
// baseline (speedup 1.0000x reference)
#include <cuda_runtime.h>
#include <math.h>

#define B_ 2
#define S_ 2048
#define D_ 1024
#define H_ 16
#define DK_ 64
#define NROWS (B_*S_)      // 4096
#define NBH (B_*H_)        // 32

// Scratch (allocation-free): module-load static device memory
__device__ float g_Q[NBH*S_*DK_];   // [b,h,s,dk]
__device__ float g_K[NBH*S_*DK_];
__device__ float g_V[NBH*S_*DK_];
__device__ float g_ctx[NROWS*D_];   // merged-head context
__device__ float g_rmax[NBH*S_];
__device__ float g_rinv[NBH*S_];

// ---------------------------------------------------------------------------
// 128x128 GEMM tile, BK=16, 256 threads, 8x8 per thread
// ---------------------------------------------------------------------------
#define PBM 128
#define PBN 128
#define PBK 16
#define PLD 132   // padded smem stride (132*4 bytes % 16 == 0 -> float4 ok)

// Kernel 1: QKV projections.  Out = X @ W^T + b, stored split-head [b,h,s,dk]
__global__ void __launch_bounds__(256) proj_kernel(
    const float* __restrict__ Xq, const float* __restrict__ Xk, const float* __restrict__ Xv,
    const float* __restrict__ Wq, const float* __restrict__ bq,
    const float* __restrict__ Wk, const float* __restrict__ bk,
    const float* __restrict__ Wv, const float* __restrict__ bv)
{
    const int which = blockIdx.z;
    const float* X    = (which == 0) ? Xq : (which == 1) ? Xk : Xv;
    const float* W    = (which == 0) ? Wq : (which == 1) ? Wk : Wv;
    const float* bias = (which == 0) ? bq : (which == 1) ? bk : bv;
    float* Out        = (which == 0) ? g_Q : (which == 1) ? g_K : g_V;

    __shared__ __align__(16) float As[PBK][PLD];
    __shared__ __align__(16) float Bs[PBK][PLD];

    const int tid  = threadIdx.x;
    const int row0 = blockIdx.y * PBM;
    const int col0 = blockIdx.x * PBN;
    const int ty = tid >> 4, tx = tid & 15;

    float acc[8][8] = {};

    for (int kb = 0; kb < D_; kb += PBK) {
        #pragma unroll
        for (int l = 0; l < 2; l++) {
            int i = tid + (l << 8);
            int ar = i >> 2, ac4 = i & 3;
            float4 v = *reinterpret_cast<const float4*>(&X[(size_t)(row0 + ar) * D_ + kb + ac4 * 4]);
            As[ac4*4+0][ar] = v.x; As[ac4*4+1][ar] = v.y;
            As[ac4*4+2][ar] = v.z; As[ac4*4+3][ar] = v.w;
        }
        #pragma unroll
        for (int l = 0; l < 2; l++) {
            int i = tid + (l << 8);
            int br = i >> 2, bc4 = i & 3;
            float4 v = *reinterpret_cast<const float4*>(&W[(size_t)(col0 + br) * D_ + kb + bc4 * 4]);
            Bs[bc4*4+0][br] = v.x; Bs[bc4*4+1][br] = v.y;
            Bs[bc4*4+2][br] = v.z; Bs[bc4*4+3][br] = v.w;
        }
        __syncthreads();
        #pragma unroll
        for (int k = 0; k < PBK; ++k) {
            float a[8], bf[8];
            *reinterpret_cast<float4*>(&a[0])  = *reinterpret_cast<const float4*>(&As[k][ty*8]);
            *reinterpret_cast<float4*>(&a[4])  = *reinterpret_cast<const float4*>(&As[k][ty*8+4]);
            *reinterpret_cast<float4*>(&bf[0]) = *reinterpret_cast<const float4*>(&Bs[k][tx*8]);
            *reinterpret_cast<float4*>(&bf[4]) = *reinterpret_cast<const float4*>(&Bs[k][tx*8+4]);
            #pragma unroll
            for (int i = 0; i < 8; i++)
                #pragma unroll
                for (int j = 0; j < 8; j++)
                    acc[i][j] = fmaf(a[i], bf[j], acc[i][j]);
        }
        __syncthreads();
    }

    // Epilogue: add bias, store split-head  Out[((b*H+h)*S + s)*DK + dk]
    #pragma unroll
    for (int i = 0; i < 8; i++) {
        int m = row0 + ty * 8 + i;
        int b = m >> 11, s = m & (S_ - 1);
        #pragma unroll
        for (int jj = 0; jj < 2; jj++) {
            int n = col0 + tx * 8 + jj * 4;
            int h = n >> 6, dk = n & (DK_ - 1);
            float4 o;
            o.x = acc[i][jj*4+0] + bias[n+0];
            o.y = acc[i][jj*4+1] + bias[n+1];
            o.z = acc[i][jj*4+2] + bias[n+2];
            o.w = acc[i][jj*4+3] + bias[n+3];
            *reinterpret_cast<float4*>(&Out[(((size_t)(b * H_ + h)) * S_ + s) * DK_ + dk]) = o;
        }
    }
}

// ---------------------------------------------------------------------------
// Kernel 2: fused scores + online softmax statistics.
// Each block owns a 128-row q strip for one (b,h): computes the full
// 128 x 2048 raw-score strip (written to attn) while tracking the running
// row max and rescaled exp-sum, then writes g_rmax / g_rinv.
// ---------------------------------------------------------------------------
__global__ void __launch_bounds__(256) scores_kernel(float* __restrict__ attn)
{
    const int bh   = blockIdx.y;
    const int row0 = blockIdx.x * PBM;
    const int tid  = threadIdx.x;
    const int ty = tid >> 4, tx = tid & 15;

    __shared__ __align__(16) float Qt[DK_][PLD];   // Q^T: [depth][128 rows]
    __shared__ __align__(16) float Ks[PBK][PLD];   // K^T chunk: [depth16][128 cols]

    const float* Qm = g_Q + ((size_t)bh * S_ + row0) * DK_;
    const float* Km = g_K + (size_t)bh * S_ * DK_;

    // Load the whole Q tile (128x64) transposed into smem, once.
    #pragma unroll
    for (int l = 0; l < 8; l++) {
        int i = tid + (l << 8);          // 0..2047
        int qr = i >> 4, qc4 = i & 15;   // row, depth-float4
        float4 v = *reinterpret_cast<const float4*>(&Qm[(size_t)qr * DK_ + qc4 * 4]);
        Qt[qc4*4+0][qr] = v.x; Qt[qc4*4+1][qr] = v.y;
        Qt[qc4*4+2][qr] = v.z; Qt[qc4*4+3][qr] = v.w;
    }

    float m_run[8], s_run[8];
    #pragma unroll
    for (int i = 0; i < 8; i++) { m_run[i] = -1e30f; s_run[i] = 0.f; }

    const float scale = 0.125f;  // 1/sqrt(64)

    for (int kt = 0; kt < S_ / 128; kt++) {
        const int col0 = kt * 128;
        float acc[8][8] = {};

        #pragma unroll
        for (int dk0 = 0; dk0 < DK_; dk0 += PBK) {
            // Load K chunk: 128 cols x 16 depths, transposed
            __syncthreads();
            #pragma unroll
            for (int l = 0; l < 2; l++) {
                int i = tid + (l << 8);
                int c = i >> 2, d4 = i & 3;
                float4 v = *reinterpret_cast<const float4*>(&Km[(size_t)(col0 + c) * DK_ + dk0 + d4 * 4]);
                Ks[d4*4+0][c] = v.x; Ks[d4*4+1][c] = v.y;
                Ks[d4*4+2][c] = v.z; Ks[d4*4+3][c] = v.w;
            }
            __syncthreads();
            #pragma unroll
            for (int k = 0; k < PBK; ++k) {
                float a[8], bf[8];
                *reinterpret_cast<float4*>(&a[0])  = *reinterpret_cast<const float4*>(&Qt[dk0+k][ty*8]);
                *reinterpret_cast<float4*>(&a[4])  = *reinterpret_cast<const float4*>(&Qt[dk0+k][ty*8+4]);
                *reinterpret_cast<float4*>(&bf[0]) = *reinterpret_cast<const float4*>(&Ks[k][tx*8]);
                *reinterpret_cast<float4*>(&bf[4]) = *reinterpret_cast<const float4*>(&Ks[k][tx*8+4]);
                #pragma unroll
                for (int i = 0; i < 8; i++)
                    #pragma unroll
                    for (int j = 0; j < 8; j++)
                        acc[i][j] = fmaf(a[i], bf[j], acc[i][j]);
            }
        }

        // Scale, write tile, update online softmax stats.
        #pragma unroll
        for (int i = 0; i < 8; i++) {
            #pragma unroll
            for (int j = 0; j < 8; j++) acc[i][j] *= scale;

            // tile row-max over this thread's 8 cols, reduced across the 16 tx lanes
            float tmax = acc[i][0];
            #pragma unroll
            for (int j = 1; j < 8; j++) tmax = fmaxf(tmax, acc[i][j]);
            #pragma unroll
            for (int o = 8; o > 0; o >>= 1)
                tmax = fmaxf(tmax, __shfl_xor_sync(0xffffffffu, tmax, o));

            float m_new = fmaxf(m_run[i], tmax);
            float ts = 0.f;
            #pragma unroll
            for (int j = 0; j < 8; j++) ts += __expf(acc[i][j] - m_new);
            #pragma unroll
            for (int o = 8; o > 0; o >>= 1)
                ts += __shfl_xor_sync(0xffffffffu, ts, o);

            s_run[i] = s_run[i] * __expf(m_run[i] - m_new) + ts;
            m_run[i] = m_new;

            int q = row0 + ty * 8 + i;
            float* wp = &attn[((size_t)bh * S_ + q) * S_ + col0 + tx * 8];
            float4 o1, o2;
            o1.x = acc[i][0]; o1.y = acc[i][1]; o1.z = acc[i][2]; o1.w = acc[i][3];
            o2.x = acc[i][4]; o2.y = acc[i][5]; o2.z = acc[i][6]; o2.w = acc[i][7];
            *reinterpret_cast<float4*>(wp)     = o1;
            *reinterpret_cast<float4*>(wp + 4) = o2;
        }
    }

    if (tx == 0) {
        #pragma unroll
        for (int i = 0; i < 8; i++) {
            int q = row0 + ty * 8 + i;
            g_rmax[bh * S_ + q] = m_run[i];
            g_rinv[bh * S_ + q] = 1.0f / s_run[i];
        }
    }
}

// ---------------------------------------------------------------------------
// Kernel 3: normalize weights in place (write softmax to d_out) AND ctx = W @ V
// 128 q x 64 dk tile, 128 threads, 8x8 per thread.
// ---------------------------------------------------------------------------
#define ALDB 68
__global__ void __launch_bounds__(128) av_kernel(float* __restrict__ attn)
{
    const int bh   = blockIdx.y;
    const int row0 = blockIdx.x * PBM;
    const int tid  = threadIdx.x;
    const int ty = tid >> 3, tx = tid & 7;

    __shared__ __align__(16) float As[PBK][PLD];
    __shared__ __align__(16) float Bs[PBK][ALDB];
    __shared__ float rmaxS[PBM], rinvS[PBM];

    rmaxS[tid]       = g_rmax[bh * S_ + row0 + tid];
    rinvS[tid]       = g_rinv[bh * S_ + row0 + tid];
    __syncthreads();

    float* Abase = attn + ((size_t)bh * S_ + row0) * S_;
    const float* Vbase = g_V + (size_t)bh * S_ * DK_;

    float acc[8][8] = {};

    for (int kb = 0; kb < S_; kb += PBK) {
        // A tile: 128 rows x 16 k. Stream: load raw score, exp-normalize,
        // write softmax weight back, stage into smem.
        #pragma unroll
        for (int l = 0; l < 4; l++) {
            int i = tid + (l << 7);      // 0..511
            int ar = i >> 2, ac4 = i & 3;
            float4* gp = reinterpret_cast<float4*>(&Abase[(size_t)ar * S_ + kb + ac4 * 4]);
            float4 v = *gp;
            float m = rmaxS[ar], inv = rinvS[ar];
            v.x = __expf(v.x - m) * inv;
            v.y = __expf(v.y - m) * inv;
            v.z = __expf(v.z - m) * inv;
            v.w = __expf(v.w - m) * inv;
            *gp = v;
            As[ac4*4+0][ar] = v.x; As[ac4*4+1][ar] = v.y;
            As[ac4*4+2][ar] = v.z; As[ac4*4+3][ar] = v.w;
        }
        // B tile: V, 16 k-rows x 64 dk
        {
            int kr = tid >> 3, c8 = (tid & 7) * 8;
            float4 v1 = *reinterpret_cast<const float4*>(&Vbase[(size_t)(kb + kr) * DK_ + c8]);
            float4 v2 = *reinterpret_cast<const float4*>(&Vbase[(size_t)(kb + kr) * DK_ + c8 + 4]);
            *reinterpret_cast<float4*>(&Bs[kr][c8])     = v1;
            *reinterpret_cast<float4*>(&Bs[kr][c8 + 4]) = v2;
        }
        __syncthreads();
        #pragma unroll
        for (int k = 0; k < PBK; ++k) {
            float a[8], bf[8];
            *reinterpret_cast<float4*>(&a[0])  = *reinterpret_cast<const float4*>(&As[k][ty*8]);
            *reinterpret_cast<float4*>(&a[4])  = *reinterpret_cast<const float4*>(&As[k][ty*8+4]);
            *reinterpret_cast<float4*>(&bf[0]) = *reinterpret_cast<const float4*>(&Bs[k][tx*8]);
            *reinterpret_cast<float4*>(&bf[4]) = *reinterpret_cast<const float4*>(&Bs[k][tx*8+4]);
            #pragma unroll
            for (int i = 0; i < 8; i++)
                #pragma unroll
                for (int j = 0; j < 8; j++)
                    acc[i][j] = fmaf(a[i], bf[j], acc[i][j]);
        }
        __syncthreads();
    }

    // Epilogue: merged-head context  g_ctx[(b*S+q)*D + h*DK + dk]
    const int b = bh >> 4, h = bh & (H_ - 1);
    #pragma unroll
    for (int i = 0; i < 8; i++) {
        int q = row0 + ty * 8 + i;
        float4 o1, o2;
        o1.x = acc[i][0]; o1.y = acc[i][1]; o1.z = acc[i][2]; o1.w = acc[i][3];
        o2.x = acc[i][4]; o2.y = acc[i][5]; o2.z = acc[i][6]; o2.w = acc[i][7];
        float* cp = &g_ctx[((size_t)(b * S_ + q)) * D_ + h * DK_ + tx * 8];
        *reinterpret_cast<float4*>(cp)     = o1;
        *reinterpret_cast<float4*>(cp + 4) = o2;
    }
}

// ---------------------------------------------------------------------------
// Kernel 4: output projection  out = ctx @ W_o^T + b_o   (128x128 tile)
// ---------------------------------------------------------------------------
__global__ void __launch_bounds__(256) outproj_kernel(
    const float* __restrict__ Wo, const float* __restrict__ bo, float* __restrict__ out)
{
    __shared__ __align__(16) float As[PBK][PLD];
    __shared__ __align__(16) float Bs[PBK][PLD];

    const int tid  = threadIdx.x;
    const int row0 = blockIdx.y * PBM;
    const int col0 = blockIdx.x * PBN;
    const int ty = tid >> 4, tx = tid & 15;
    float acc[8][8] = {};

    for (int kb = 0; kb < D_; kb += PBK) {
        #pragma unroll
        for (int l = 0; l < 2; l++) {
            int i = tid + (l << 8);
            int ar = i >> 2, ac4 = i & 3;
            float4 v = *reinterpret_cast<const float4*>(&g_ctx[(size_t)(row0 + ar) * D_ + kb + ac4 * 4]);
            As[ac4*4+0][ar] = v.x; As[ac4*4+1][ar] = v.y;
            As[ac4*4+2][ar] = v.z; As[ac4*4+3][ar] = v.w;
        }
        #pragma unroll
        for (int l = 0; l < 2; l++) {
            int i = tid + (l << 8);
            int br = i >> 2, bc4 = i & 3;
            float4 v = *reinterpret_cast<const float4*>(&Wo[(size_t)(col0 + br) * D_ + kb + bc4 * 4]);
            Bs[bc4*4+0][br] = v.x; Bs[bc4*4+1][br] = v.y;
            Bs[bc4*4+2][br] = v.z; Bs[bc4*4+3][br] = v.w;
        }
        __syncthreads();
        #pragma unroll
        for (int k = 0; k < PBK; ++k) {
            float a[8], bf[8];
            *reinterpret_cast<float4*>(&a[0])  = *reinterpret_cast<const float4*>(&As[k][ty*8]);
            *reinterpret_cast<float4*>(&a[4])  = *reinterpret_cast<const float4*>(&As[k][ty*8+4]);
            *reinterpret_cast<float4*>(&bf[0]) = *reinterpret_cast<const float4*>(&Bs[k][tx*8]);
            *reinterpret_cast<float4*>(&bf[4]) = *reinterpret_cast<const float4*>(&Bs[k][tx*8+4]);
            #pragma unroll
            for (int i = 0; i < 8; i++)
                #pragma unroll
                for (int j = 0; j < 8; j++)
                    acc[i][j] = fmaf(a[i], bf[j], acc[i][j]);
        }
        __syncthreads();
    }

    #pragma unroll
    for (int i = 0; i < 8; i++) {
        int m = row0 + ty * 8 + i;
        #pragma unroll
        for (int jj = 0; jj < 2; jj++) {
            int n = col0 + tx * 8 + jj * 4;
            float4 o;
            o.x = acc[i][jj*4+0] + bo[n + 0];
            o.y = acc[i][jj*4+1] + bo[n + 1];
            o.z = acc[i][jj*4+2] + bo[n + 2];
            o.w = acc[i][jj*4+3] + bo[n + 3];
            *reinterpret_cast<float4*>(&out[(size_t)m * D_ + n]) = o;
        }
    }
}

// ---------------------------------------------------------------------------
extern "C" void kernel_launch(void* const* d_in, const int* in_sizes, int n_in,
                              void* d_out, int out_size)
{
    const float* query = (const float*)d_in[0];
    const float* key_  = (const float*)d_in[1];
    const float* value = (const float*)d_in[2];
    const float* W_q = (const float*)d_in[3];
    const float* b_q = (const float*)d_in[4];
    const float* W_k = (const float*)d_in[5];
    const float* b_k = (const float*)d_in[6];
    const float* W_v = (const float*)d_in[7];
    const float* b_v = (const float*)d_in[8];
    const float* W_o = (const float*)d_in[9];
    const float* b_o = (const float*)d_in[10];

    float* out  = (float*)d_out;                       // [B,S,D]
    float* attn = out + (size_t)B_ * S_ * D_;          // [B,H,S,S]

    proj_kernel<<<dim3(D_/PBN, NROWS/PBM, 3), 256>>>(
        query, key_, value, W_q, b_q, W_k, b_k, W_v, b_v);

    scores_kernel<<<dim3(S_/PBM, NBH), 256>>>(attn);

    av_kernel<<<dim3(S_/PBM, NBH), 128>>>(attn);

    outproj_kernel<<<dim3(D_/PBN, NROWS/PBM), 256>>>(W_o, b_o, out);
}

// round 5
// speedup vs baseline: 1.1725x; 1.1725x over previous
#include <cuda_runtime.h>
#include <math.h>

#define B_ 2
#define S_ 2048
#define D_ 1024
#define H_ 16
#define DK_ 64
#define NROWS (B_*S_)      // 4096
#define NBH (B_*H_)        // 32

// Scratch (allocation-free): module-load static device memory
__device__ float g_Q[NBH*S_*DK_];   // [b,h,s,dk]
__device__ float g_K[NBH*S_*DK_];
__device__ float g_V[NBH*S_*DK_];
__device__ float g_ctx[(size_t)NROWS*D_];
__device__ float g_rmax[NBH*S_];
__device__ float g_rinv[NBH*S_];

// ---------------------------------------------------------------------------
// tf32 helpers: 3xTF32 error-compensated MMA (hi*hi + hi*lo + lo*hi)
// ---------------------------------------------------------------------------
__device__ __forceinline__ unsigned cvt_tf32(float f) {
    unsigned u; asm("cvt.rna.tf32.f32 %0, %1;" : "=r"(u) : "f"(f)); return u;
}
__device__ __forceinline__ void split1(float f, unsigned &h, unsigned &l) {
    h = cvt_tf32(f);
    l = cvt_tf32(f - __uint_as_float(h));
}
__device__ __forceinline__ void split4(unsigned* h, unsigned* l, float4 v) {
    split1(v.x, h[0], l[0]); split1(v.y, h[1], l[1]);
    split1(v.z, h[2], l[2]); split1(v.w, h[3], l[3]);
}
// m16n8k8 tf32 mma, accumulate into c[4]
__device__ __forceinline__ void mma8(float* c, const unsigned* a, unsigned b0, unsigned b1) {
    asm volatile(
        "mma.sync.aligned.m16n8k8.row.col.f32.tf32.tf32.f32 "
        "{%0,%1,%2,%3},{%4,%5,%6,%7},{%8,%9},{%0,%1,%2,%3};\n"
        : "+f"(c[0]), "+f"(c[1]), "+f"(c[2]), "+f"(c[3])
        : "r"(a[0]), "r"(a[1]), "r"(a[2]), "r"(a[3]), "r"(b0), "r"(b1));
}

// Fragment indexing (per PTX m16n8k8 tf32):
//  g = (lane>>2), tg = lane&3
//  A[m][k]: a0=(g,tg) a1=(g+8,tg) a2=(g,tg+4) a3=(g+8,tg+4)
//  B[k][n]: b0=(tg,g) b1=(tg+4,g)
//  C[m][n]: c0=(g,2tg) c1=(g,2tg+1) c2=(g+8,2tg) c3=(g+8,2tg+1)

#define PSTR 36   // smem row stride (u32) for [row][k<=32] tiles; 4g+tg banks distinct
#define VSTR 72   // smem row stride for V [k][64 n] tiles; 64 cols + pad, 8tg+g banks distinct

// ---------------------------------------------------------------------------
// Kernel 1: QKV projections (3xTF32).  Out = X @ W^T + b, split-head store.
// 128x128 block tile, BK=32, 256 threads, 8 warps (2m x 4n), warp tile 64x32.
// ---------------------------------------------------------------------------
__global__ void __launch_bounds__(256) proj_kernel(
    const float* __restrict__ Xq, const float* __restrict__ Xk, const float* __restrict__ Xv,
    const float* __restrict__ Wq, const float* __restrict__ bq,
    const float* __restrict__ Wk, const float* __restrict__ bk,
    const float* __restrict__ Wv, const float* __restrict__ bv)
{
    const int which = blockIdx.z;
    const float* X    = (which == 0) ? Xq : (which == 1) ? Xk : Xv;
    const float* W    = (which == 0) ? Wq : (which == 1) ? Wk : Wv;
    const float* bias = (which == 0) ? bq : (which == 1) ? bk : bv;
    float* Out        = (which == 0) ? g_Q : (which == 1) ? g_K : g_V;

    extern __shared__ unsigned sm[];
    unsigned (*Ah)[PSTR] = (unsigned(*)[PSTR])sm;
    unsigned (*Al)[PSTR] = Ah + 128;
    unsigned (*Bh)[PSTR] = Al + 128;
    unsigned (*Bl)[PSTR] = Bh + 128;

    const int tid = threadIdx.x;
    const int warp = tid >> 5;
    const int g = (tid >> 2) & 7, tg = tid & 3;
    const int wm0 = (warp & 1) * 64, wn0 = (warp >> 1) * 32;
    const int row0 = blockIdx.y * 128;
    const int col0 = blockIdx.x * 128;

    float acc[4][4][4] = {};

    for (int kb = 0; kb < D_; kb += 32) {
        #pragma unroll
        for (int p = 0; p < 4; p++) {
            int lin = tid + (p << 8);
            int r = lin >> 3, c = (lin & 7) << 2;
            float4 v = *reinterpret_cast<const float4*>(X + (size_t)(row0 + r) * D_ + kb + c);
            split4(&Ah[r][c], &Al[r][c], v);
        }
        #pragma unroll
        for (int p = 0; p < 4; p++) {
            int lin = tid + (p << 8);
            int r = lin >> 3, c = (lin & 7) << 2;
            float4 v = *reinterpret_cast<const float4*>(W + (size_t)(col0 + r) * D_ + kb + c);
            split4(&Bh[r][c], &Bl[r][c], v);
        }
        __syncthreads();
        #pragma unroll
        for (int ks = 0; ks < 32; ks += 8) {
            unsigned ah[4][4], al[4][4];
            #pragma unroll
            for (int mf = 0; mf < 4; mf++) {
                int r = wm0 + mf * 16;
                ah[mf][0] = Ah[r+g  ][ks+tg]; ah[mf][1] = Ah[r+g+8][ks+tg];
                ah[mf][2] = Ah[r+g  ][ks+tg+4]; ah[mf][3] = Ah[r+g+8][ks+tg+4];
                al[mf][0] = Al[r+g  ][ks+tg]; al[mf][1] = Al[r+g+8][ks+tg];
                al[mf][2] = Al[r+g  ][ks+tg+4]; al[mf][3] = Al[r+g+8][ks+tg+4];
            }
            #pragma unroll
            for (int nf = 0; nf < 4; nf++) {
                int r = wn0 + nf * 8 + g;
                unsigned bh0 = Bh[r][ks+tg], bh1 = Bh[r][ks+tg+4];
                unsigned bl0 = Bl[r][ks+tg], bl1 = Bl[r][ks+tg+4];
                #pragma unroll
                for (int mf = 0; mf < 4; mf++) {
                    mma8(acc[mf][nf], ah[mf], bh0, bh1);
                    mma8(acc[mf][nf], ah[mf], bl0, bl1);
                    mma8(acc[mf][nf], al[mf], bh0, bh1);
                }
            }
        }
        __syncthreads();
    }

    // Epilogue: bias + split-head store Out[((b*H+h)*S+s)*DK+dk]
    #pragma unroll
    for (int nf = 0; nf < 4; nf++) {
        int n0 = col0 + wn0 + nf * 8 + 2 * tg;
        float b0v = bias[n0], b1v = bias[n0 + 1];
        int h = n0 >> 6, dk = n0 & (DK_ - 1);
        #pragma unroll
        for (int mf = 0; mf < 4; mf++) {
            int m = row0 + wm0 + mf * 16 + g;
            int b = m >> 11, s = m & (S_ - 1);
            size_t base = (((size_t)(b * H_ + h)) * S_) * DK_ + dk;
            float2 o0 = make_float2(acc[mf][nf][0] + b0v, acc[mf][nf][1] + b1v);
            float2 o1 = make_float2(acc[mf][nf][2] + b0v, acc[mf][nf][3] + b1v);
            *reinterpret_cast<float2*>(&Out[base + (size_t)s * DK_])       = o0;
            *reinterpret_cast<float2*>(&Out[base + (size_t)(s + 8) * DK_]) = o1;
        }
    }
}

// ---------------------------------------------------------------------------
// Kernel 2: scores = (Q*scale) @ K^T  (3xTF32), raw scores -> attn
// 128(q) x 128(kcol) block tile, K-dim = DK = 64 in two 32-chunks.
// ---------------------------------------------------------------------------
__global__ void __launch_bounds__(256) scores_kernel(float* __restrict__ attn)
{
    extern __shared__ unsigned sm[];
    unsigned (*Ah)[PSTR] = (unsigned(*)[PSTR])sm;
    unsigned (*Al)[PSTR] = Ah + 128;
    unsigned (*Bh)[PSTR] = Al + 128;
    unsigned (*Bl)[PSTR] = Bh + 128;

    const int bh   = blockIdx.z;
    const int row0 = blockIdx.y * 128;   // q
    const int col0 = blockIdx.x * 128;   // kcol
    const int tid = threadIdx.x;
    const int warp = tid >> 5;
    const int g = (tid >> 2) & 7, tg = tid & 3;
    const int wm0 = (warp & 1) * 64, wn0 = (warp >> 1) * 32;

    const float* Qm = g_Q + ((size_t)bh * S_ + row0) * DK_;
    const float* Km = g_K + ((size_t)bh * S_ + col0) * DK_;

    float acc[4][4][4] = {};

    #pragma unroll
    for (int kb = 0; kb < DK_; kb += 32) {
        #pragma unroll
        for (int p = 0; p < 4; p++) {
            int lin = tid + (p << 8);
            int r = lin >> 3, c = (lin & 7) << 2;
            float4 v = *reinterpret_cast<const float4*>(Qm + (size_t)r * DK_ + kb + c);
            v.x *= 0.125f; v.y *= 0.125f; v.z *= 0.125f; v.w *= 0.125f;  // fold 1/sqrt(DK)
            split4(&Ah[r][c], &Al[r][c], v);
        }
        #pragma unroll
        for (int p = 0; p < 4; p++) {
            int lin = tid + (p << 8);
            int r = lin >> 3, c = (lin & 7) << 2;
            float4 v = *reinterpret_cast<const float4*>(Km + (size_t)r * DK_ + kb + c);
            split4(&Bh[r][c], &Bl[r][c], v);
        }
        __syncthreads();
        #pragma unroll
        for (int ks = 0; ks < 32; ks += 8) {
            unsigned ah[4][4], al[4][4];
            #pragma unroll
            for (int mf = 0; mf < 4; mf++) {
                int r = wm0 + mf * 16;
                ah[mf][0] = Ah[r+g  ][ks+tg]; ah[mf][1] = Ah[r+g+8][ks+tg];
                ah[mf][2] = Ah[r+g  ][ks+tg+4]; ah[mf][3] = Ah[r+g+8][ks+tg+4];
                al[mf][0] = Al[r+g  ][ks+tg]; al[mf][1] = Al[r+g+8][ks+tg];
                al[mf][2] = Al[r+g  ][ks+tg+4]; al[mf][3] = Al[r+g+8][ks+tg+4];
            }
            #pragma unroll
            for (int nf = 0; nf < 4; nf++) {
                int r = wn0 + nf * 8 + g;
                unsigned bh0 = Bh[r][ks+tg], bh1 = Bh[r][ks+tg+4];
                unsigned bl0 = Bl[r][ks+tg], bl1 = Bl[r][ks+tg+4];
                #pragma unroll
                for (int mf = 0; mf < 4; mf++) {
                    mma8(acc[mf][nf], ah[mf], bh0, bh1);
                    mma8(acc[mf][nf], ah[mf], bl0, bl1);
                    mma8(acc[mf][nf], al[mf], bh0, bh1);
                }
            }
        }
        __syncthreads();
    }

    #pragma unroll
    for (int nf = 0; nf < 4; nf++) {
        int c0 = col0 + wn0 + nf * 8 + 2 * tg;
        #pragma unroll
        for (int mf = 0; mf < 4; mf++) {
            int q = row0 + wm0 + mf * 16 + g;
            float2 o0 = make_float2(acc[mf][nf][0], acc[mf][nf][1]);
            float2 o1 = make_float2(acc[mf][nf][2], acc[mf][nf][3]);
            *reinterpret_cast<float2*>(&attn[((size_t)bh * S_ + q) * S_ + c0])       = o0;
            *reinterpret_cast<float2*>(&attn[((size_t)bh * S_ + q + 8) * S_ + c0])   = o1;
        }
    }
}

// ---------------------------------------------------------------------------
// Kernel 3: per-row max and 1/sum(exp) over the raw scores
// ---------------------------------------------------------------------------
__global__ void __launch_bounds__(256) rowstat_kernel(const float* __restrict__ attn)
{
    const int row = blockIdx.x;                 // [0, NBH*S)
    const float* p = attn + (size_t)row * S_;
    const int tid = threadIdx.x;

    float v[8];
    float mx = -1e30f;
    #pragma unroll
    for (int i = 0; i < 8; i++) { v[i] = p[tid + (i << 8)]; mx = fmaxf(mx, v[i]); }

    __shared__ float red[8];
    #pragma unroll
    for (int o = 16; o > 0; o >>= 1) mx = fmaxf(mx, __shfl_xor_sync(0xffffffffu, mx, o));
    int warp = tid >> 5, lane = tid & 31;
    if (lane == 0) red[warp] = mx;
    __syncthreads();
    if (tid < 8) {
        float m = red[tid];
        #pragma unroll
        for (int o = 4; o > 0; o >>= 1) m = fmaxf(m, __shfl_xor_sync(0xffu, m, o));
        if (tid == 0) red[0] = m;
    }
    __syncthreads();
    mx = red[0];
    __syncthreads();

    float sum = 0.f;
    #pragma unroll
    for (int i = 0; i < 8; i++) sum += __expf(v[i] - mx);
    #pragma unroll
    for (int o = 16; o > 0; o >>= 1) sum += __shfl_xor_sync(0xffffffffu, sum, o);
    if (lane == 0) red[warp] = sum;
    __syncthreads();
    if (tid == 0) {
        float s = 0.f;
        #pragma unroll
        for (int w = 0; w < 8; w++) s += red[w];
        g_rmax[row] = mx;
        g_rinv[row] = 1.0f / s;
    }
}

// ---------------------------------------------------------------------------
// Kernel 4: normalize weights in place AND ctx = W @ V  (3xTF32)
// Block: 128 q x 64 dk (full), loop kcol in 32-chunks. 8 warps (4m x 2n),
// warp tile 32x32, mfrags=2, nfrags=4.  Dynamic smem.
// ---------------------------------------------------------------------------
__global__ void __launch_bounds__(256) av_kernel(float* __restrict__ attn)
{
    extern __shared__ unsigned sm[];
    unsigned (*AhS)[PSTR] = (unsigned(*)[PSTR])sm;                  // 128*36
    unsigned (*AlS)[PSTR] = AhS + 128;                              // 128*36
    unsigned (*VhS)[VSTR] = (unsigned(*)[VSTR])(AlS + 128);         // 32*72
    unsigned (*VlS)[VSTR] = VhS + 32;                               // 32*72
    float* rmaxS = (float*)(VlS + 32);                              // 128
    float* rinvS = rmaxS + 128;                                     // 128

    const int bh   = blockIdx.y;
    const int row0 = blockIdx.x * 128;
    const int tid  = threadIdx.x;
    const int warp = tid >> 5;
    const int g = (tid >> 2) & 7, tg = tid & 3;
    const int wm0 = (warp & 3) * 32, wn0 = (warp >> 2) * 32;

    if (tid < 128) {
        rmaxS[tid] = g_rmax[bh * S_ + row0 + tid];
        rinvS[tid] = g_rinv[bh * S_ + row0 + tid];
    }
    __syncthreads();

    float* Abase = attn + ((size_t)bh * S_ + row0) * S_;
    const float* Vbase = g_V + (size_t)bh * S_ * DK_;

    float acc[2][4][4] = {};

    for (int kb = 0; kb < S_; kb += 32) {
        // scores chunk: read raw, softmax-normalize, write back, split-stage
        #pragma unroll
        for (int p = 0; p < 4; p++) {
            int lin = tid + (p << 8);
            int r = lin >> 3, c = (lin & 7) << 2;
            float4* gp = reinterpret_cast<float4*>(Abase + (size_t)r * S_ + kb + c);
            float4 v = *gp;
            float m = rmaxS[r], inv = rinvS[r];
            v.x = __expf(v.x - m) * inv;
            v.y = __expf(v.y - m) * inv;
            v.z = __expf(v.z - m) * inv;
            v.w = __expf(v.w - m) * inv;
            *gp = v;
            split4(&AhS[r][c], &AlS[r][c], v);
        }
        // V chunk: 32 kcol-rows x 64 dk, stored [k][n]
        #pragma unroll
        for (int p = 0; p < 2; p++) {
            int lin = tid + (p << 8);
            int r = lin >> 4, c = (lin & 15) << 2;
            float4 v = *reinterpret_cast<const float4*>(Vbase + (size_t)(kb + r) * DK_ + c);
            split4(&VhS[r][c], &VlS[r][c], v);
        }
        __syncthreads();
        #pragma unroll
        for (int ks = 0; ks < 32; ks += 8) {
            unsigned ah[2][4], al[2][4];
            #pragma unroll
            for (int mf = 0; mf < 2; mf++) {
                int r = wm0 + mf * 16;
                ah[mf][0] = AhS[r+g  ][ks+tg]; ah[mf][1] = AhS[r+g+8][ks+tg];
                ah[mf][2] = AhS[r+g  ][ks+tg+4]; ah[mf][3] = AhS[r+g+8][ks+tg+4];
                al[mf][0] = AlS[r+g  ][ks+tg]; al[mf][1] = AlS[r+g+8][ks+tg];
                al[mf][2] = AlS[r+g  ][ks+tg+4]; al[mf][3] = AlS[r+g+8][ks+tg+4];
            }
            #pragma unroll
            for (int nf = 0; nf < 4; nf++) {
                int vn = wn0 + nf * 8 + g;
                unsigned bh0 = VhS[ks+tg][vn], bh1 = VhS[ks+tg+4][vn];
                unsigned bl0 = VlS[ks+tg][vn], bl1 = VlS[ks+tg+4][vn];
                #pragma unroll
                for (int mf = 0; mf < 2; mf++) {
                    mma8(acc[mf][nf], ah[mf], bh0, bh1);
                    mma8(acc[mf][nf], ah[mf], bl0, bl1);
                    mma8(acc[mf][nf], al[mf], bh0, bh1);
                }
            }
        }
        __syncthreads();
    }

    // Epilogue: merged-head context  g_ctx[(b*S+q)*D + h*DK + c]
    const int b = bh >> 4, h = bh & (H_ - 1);
    #pragma unroll
    for (int nf = 0; nf < 4; nf++) {
        int c0 = wn0 + nf * 8 + 2 * tg;
        #pragma unroll
        for (int mf = 0; mf < 2; mf++) {
            int q = row0 + wm0 + mf * 16 + g;
            float2 o0 = make_float2(acc[mf][nf][0], acc[mf][nf][1]);
            float2 o1 = make_float2(acc[mf][nf][2], acc[mf][nf][3]);
            *reinterpret_cast<float2*>(&g_ctx[((size_t)(b * S_ + q))     * D_ + h * DK_ + c0]) = o0;
            *reinterpret_cast<float2*>(&g_ctx[((size_t)(b * S_ + q + 8)) * D_ + h * DK_ + c0]) = o1;
        }
    }
}

// ---------------------------------------------------------------------------
// Kernel 5: output projection out = ctx @ W_o^T + b_o  (3xTF32)
// ---------------------------------------------------------------------------
__global__ void __launch_bounds__(256) outproj_kernel(
    const float* __restrict__ Wo, const float* __restrict__ bo, float* __restrict__ out)
{
    extern __shared__ unsigned sm[];
    unsigned (*Ah)[PSTR] = (unsigned(*)[PSTR])sm;
    unsigned (*Al)[PSTR] = Ah + 128;
    unsigned (*Bh)[PSTR] = Al + 128;
    unsigned (*Bl)[PSTR] = Bh + 128;

    const int tid = threadIdx.x;
    const int warp = tid >> 5;
    const int g = (tid >> 2) & 7, tg = tid & 3;
    const int wm0 = (warp & 1) * 64, wn0 = (warp >> 1) * 32;
    const int row0 = blockIdx.y * 128;
    const int col0 = blockIdx.x * 128;

    float acc[4][4][4] = {};

    for (int kb = 0; kb < D_; kb += 32) {
        #pragma unroll
        for (int p = 0; p < 4; p++) {
            int lin = tid + (p << 8);
            int r = lin >> 3, c = (lin & 7) << 2;
            float4 v = *reinterpret_cast<const float4*>(g_ctx + (size_t)(row0 + r) * D_ + kb + c);
            split4(&Ah[r][c], &Al[r][c], v);
        }
        #pragma unroll
        for (int p = 0; p < 4; p++) {
            int lin = tid + (p << 8);
            int r = lin >> 3, c = (lin & 7) << 2;
            float4 v = *reinterpret_cast<const float4*>(Wo + (size_t)(col0 + r) * D_ + kb + c);
            split4(&Bh[r][c], &Bl[r][c], v);
        }
        __syncthreads();
        #pragma unroll
        for (int ks = 0; ks < 32; ks += 8) {
            unsigned ah[4][4], al[4][4];
            #pragma unroll
            for (int mf = 0; mf < 4; mf++) {
                int r = wm0 + mf * 16;
                ah[mf][0] = Ah[r+g  ][ks+tg]; ah[mf][1] = Ah[r+g+8][ks+tg];
                ah[mf][2] = Ah[r+g  ][ks+tg+4]; ah[mf][3] = Ah[r+g+8][ks+tg+4];
                al[mf][0] = Al[r+g  ][ks+tg]; al[mf][1] = Al[r+g+8][ks+tg];
                al[mf][2] = Al[r+g  ][ks+tg+4]; al[mf][3] = Al[r+g+8][ks+tg+4];
            }
            #pragma unroll
            for (int nf = 0; nf < 4; nf++) {
                int r = wn0 + nf * 8 + g;
                unsigned bh0 = Bh[r][ks+tg], bh1 = Bh[r][ks+tg+4];
                unsigned bl0 = Bl[r][ks+tg], bl1 = Bl[r][ks+tg+4];
                #pragma unroll
                for (int mf = 0; mf < 4; mf++) {
                    mma8(acc[mf][nf], ah[mf], bh0, bh1);
                    mma8(acc[mf][nf], ah[mf], bl0, bl1);
                    mma8(acc[mf][nf], al[mf], bh0, bh1);
                }
            }
        }
        __syncthreads();
    }

    #pragma unroll
    for (int nf = 0; nf < 4; nf++) {
        int n0 = col0 + wn0 + nf * 8 + 2 * tg;
        float b0v = bo[n0], b1v = bo[n0 + 1];
        #pragma unroll
        for (int mf = 0; mf < 4; mf++) {
            int m = row0 + wm0 + mf * 16 + g;
            float2 o0 = make_float2(acc[mf][nf][0] + b0v, acc[mf][nf][1] + b1v);
            float2 o1 = make_float2(acc[mf][nf][2] + b0v, acc[mf][nf][3] + b1v);
            *reinterpret_cast<float2*>(&out[(size_t)m * D_ + n0])       = o0;
            *reinterpret_cast<float2*>(&out[(size_t)(m + 8) * D_ + n0]) = o1;
        }
    }
}

// ---------------------------------------------------------------------------
extern "C" void kernel_launch(void* const* d_in, const int* in_sizes, int n_in,
                              void* d_out, int out_size)
{
    const float* query = (const float*)d_in[0];
    const float* key_  = (const float*)d_in[1];
    const float* value = (const float*)d_in[2];
    const float* W_q = (const float*)d_in[3];
    const float* b_q = (const float*)d_in[4];
    const float* W_k = (const float*)d_in[5];
    const float* b_k = (const float*)d_in[6];
    const float* W_v = (const float*)d_in[7];
    const float* b_v = (const float*)d_in[8];
    const float* W_o = (const float*)d_in[9];
    const float* b_o = (const float*)d_in[10];

    float* out  = (float*)d_out;                       // [B,S,D]
    float* attn = out + (size_t)B_ * S_ * D_;          // [B,H,S,S]

    const int DSMEM  = 4 * 128 * PSTR * sizeof(unsigned);                       // 73728 B
    const int AVSMEM = (2 * 128 * PSTR + 2 * 32 * VSTR) * sizeof(unsigned)
                     + 2 * 128 * sizeof(float);                                 // 56320 B
    cudaFuncSetAttribute(proj_kernel,    cudaFuncAttributeMaxDynamicSharedMemorySize, DSMEM);
    cudaFuncSetAttribute(scores_kernel,  cudaFuncAttributeMaxDynamicSharedMemorySize, DSMEM);
    cudaFuncSetAttribute(av_kernel,      cudaFuncAttributeMaxDynamicSharedMemorySize, AVSMEM);
    cudaFuncSetAttribute(outproj_kernel, cudaFuncAttributeMaxDynamicSharedMemorySize, DSMEM);

    proj_kernel<<<dim3(D_/128, NROWS/128, 3), 256, DSMEM>>>(
        query, key_, value, W_q, b_q, W_k, b_k, W_v, b_v);

    scores_kernel<<<dim3(S_/128, S_/128, NBH), 256, DSMEM>>>(attn);

    rowstat_kernel<<<NBH * S_, 256>>>(attn);

    av_kernel<<<dim3(S_/128, NBH), 256, AVSMEM>>>(attn);

    outproj_kernel<<<dim3(D_/128, NROWS/128), 256, DSMEM>>>(W_o, b_o, out);
}

// round 6
// speedup vs baseline: 1.2881x; 1.0986x over previous
#include <cuda_runtime.h>
#include <math.h>

#define B_ 2
#define S_ 2048
#define D_ 1024
#define H_ 16
#define DK_ 64
#define NROWS (B_*S_)      // 4096
#define NBH (B_*H_)        // 32

// Scratch (allocation-free): module-load static device memory
__device__ float g_Q[NBH*S_*DK_];   // [b,h,s,dk]
__device__ float g_K[NBH*S_*DK_];
__device__ float g_V[NBH*S_*DK_];
__device__ float g_ctx[(size_t)NROWS*D_];
__device__ float g_rmax[NBH*S_];
__device__ float g_rinv[NBH*S_];

// ---------------------------------------------------------------------------
// tf32 helpers
// ---------------------------------------------------------------------------
__device__ __forceinline__ unsigned cvt_tf32(float f) {
    unsigned u; asm("cvt.rna.tf32.f32 %0, %1;" : "=r"(u) : "f"(f)); return u;
}
__device__ __forceinline__ void split1(float f, unsigned &h, unsigned &l) {
    h = cvt_tf32(f);
    l = cvt_tf32(f - __uint_as_float(h));
}
__device__ __forceinline__ void split4(unsigned* h, unsigned* l, float4 v) {
    split1(v.x, h[0], l[0]); split1(v.y, h[1], l[1]);
    split1(v.z, h[2], l[2]); split1(v.w, h[3], l[3]);
}
__device__ __forceinline__ void cvt4(unsigned* h, float4 v) {
    h[0] = cvt_tf32(v.x); h[1] = cvt_tf32(v.y);
    h[2] = cvt_tf32(v.z); h[3] = cvt_tf32(v.w);
}
// m16n8k8 tf32 mma, accumulate into c[4]
__device__ __forceinline__ void mma8(float* c, const unsigned* a, unsigned b0, unsigned b1) {
    asm volatile(
        "mma.sync.aligned.m16n8k8.row.col.f32.tf32.tf32.f32 "
        "{%0,%1,%2,%3},{%4,%5,%6,%7},{%8,%9},{%0,%1,%2,%3};\n"
        : "+f"(c[0]), "+f"(c[1]), "+f"(c[2]), "+f"(c[3])
        : "r"(a[0]), "r"(a[1]), "r"(a[2]), "r"(a[3]), "r"(b0), "r"(b1));
}

#define PSTR 36   // smem row stride (u32) for [row][k<=32] tiles (36%32=4 -> 4g+tg distinct)
#define QSTR 68   // smem row stride for [row][64] Q tiles (68%32=4)
#define VSTR 72   // smem row stride for V [k][64 n] tiles (72%32=8 -> 8tg+g distinct)

// ---------------------------------------------------------------------------
// Kernel 1: QKV projections (3xTF32).  Out = X @ W^T + b, split-head store.
// 128x128 block tile, BK=32, 256 threads, 8 warps (2m x 4n), warp tile 64x32.
// ---------------------------------------------------------------------------
__global__ void __launch_bounds__(256) proj_kernel(
    const float* __restrict__ Xq, const float* __restrict__ Xk, const float* __restrict__ Xv,
    const float* __restrict__ Wq, const float* __restrict__ bq,
    const float* __restrict__ Wk, const float* __restrict__ bk,
    const float* __restrict__ Wv, const float* __restrict__ bv)
{
    const int which = blockIdx.z;
    const float* X    = (which == 0) ? Xq : (which == 1) ? Xk : Xv;
    const float* W    = (which == 0) ? Wq : (which == 1) ? Wk : Wv;
    const float* bias = (which == 0) ? bq : (which == 1) ? bk : bv;
    float* Out        = (which == 0) ? g_Q : (which == 1) ? g_K : g_V;

    extern __shared__ unsigned sm[];
    unsigned (*Ah)[PSTR] = (unsigned(*)[PSTR])sm;
    unsigned (*Al)[PSTR] = Ah + 128;
    unsigned (*Bh)[PSTR] = Al + 128;
    unsigned (*Bl)[PSTR] = Bh + 128;

    const int tid = threadIdx.x;
    const int warp = tid >> 5;
    const int g = (tid >> 2) & 7, tg = tid & 3;
    const int wm0 = (warp & 1) * 64, wn0 = (warp >> 1) * 32;
    const int row0 = blockIdx.y * 128;
    const int col0 = blockIdx.x * 128;

    float acc[4][4][4] = {};

    for (int kb = 0; kb < D_; kb += 32) {
        #pragma unroll
        for (int p = 0; p < 4; p++) {
            int lin = tid + (p << 8);
            int r = lin >> 3, c = (lin & 7) << 2;
            float4 v = *reinterpret_cast<const float4*>(X + (size_t)(row0 + r) * D_ + kb + c);
            split4(&Ah[r][c], &Al[r][c], v);
        }
        #pragma unroll
        for (int p = 0; p < 4; p++) {
            int lin = tid + (p << 8);
            int r = lin >> 3, c = (lin & 7) << 2;
            float4 v = *reinterpret_cast<const float4*>(W + (size_t)(col0 + r) * D_ + kb + c);
            split4(&Bh[r][c], &Bl[r][c], v);
        }
        __syncthreads();
        #pragma unroll
        for (int ks = 0; ks < 32; ks += 8) {
            unsigned ah[4][4], al[4][4];
            #pragma unroll
            for (int mf = 0; mf < 4; mf++) {
                int r = wm0 + mf * 16;
                ah[mf][0] = Ah[r+g  ][ks+tg]; ah[mf][1] = Ah[r+g+8][ks+tg];
                ah[mf][2] = Ah[r+g  ][ks+tg+4]; ah[mf][3] = Ah[r+g+8][ks+tg+4];
                al[mf][0] = Al[r+g  ][ks+tg]; al[mf][1] = Al[r+g+8][ks+tg];
                al[mf][2] = Al[r+g  ][ks+tg+4]; al[mf][3] = Al[r+g+8][ks+tg+4];
            }
            #pragma unroll
            for (int nf = 0; nf < 4; nf++) {
                int r = wn0 + nf * 8 + g;
                unsigned bh0 = Bh[r][ks+tg], bh1 = Bh[r][ks+tg+4];
                unsigned bl0 = Bl[r][ks+tg], bl1 = Bl[r][ks+tg+4];
                #pragma unroll
                for (int mf = 0; mf < 4; mf++) {
                    mma8(acc[mf][nf], ah[mf], bh0, bh1);
                    mma8(acc[mf][nf], ah[mf], bl0, bl1);
                    mma8(acc[mf][nf], al[mf], bh0, bh1);
                }
            }
        }
        __syncthreads();
    }

    // Epilogue: bias + split-head store Out[((b*H+h)*S+s)*DK+dk]
    #pragma unroll
    for (int nf = 0; nf < 4; nf++) {
        int n0 = col0 + wn0 + nf * 8 + 2 * tg;
        float b0v = bias[n0], b1v = bias[n0 + 1];
        int h = n0 >> 6, dk = n0 & (DK_ - 1);
        #pragma unroll
        for (int mf = 0; mf < 4; mf++) {
            int m = row0 + wm0 + mf * 16 + g;
            int b = m >> 11, s = m & (S_ - 1);
            size_t base = (((size_t)(b * H_ + h)) * S_) * DK_ + dk;
            float2 o0 = make_float2(acc[mf][nf][0] + b0v, acc[mf][nf][1] + b1v);
            float2 o1 = make_float2(acc[mf][nf][2] + b0v, acc[mf][nf][3] + b1v);
            *reinterpret_cast<float2*>(&Out[base + (size_t)s * DK_])       = o0;
            *reinterpret_cast<float2*>(&Out[base + (size_t)(s + 8) * DK_]) = o1;
        }
    }
}

// ---------------------------------------------------------------------------
// Kernel 2: scores = (Q*scale) @ K^T  (3xTF32) + fused online softmax stats.
// One block owns a full 128-row q strip (128 x 2048) for one (b,h).
// Warp layout: 8 warps, each owns 16 q rows; 16 n-fragments cover 128 cols.
// Q (scaled, split) staged once in smem; K staged per 128-col tile in two
// 32-depth chunks. Row stats reduced with 2 shuffles (tg quad owns the row).
// ---------------------------------------------------------------------------
__global__ void __launch_bounds__(256) scores_kernel(float* __restrict__ attn)
{
    extern __shared__ unsigned sm[];
    unsigned (*Qh)[QSTR] = (unsigned(*)[QSTR])sm;           // 128 x 68
    unsigned (*Ql)[QSTR] = Qh + 128;                        // 128 x 68
    unsigned (*Kh)[PSTR] = (unsigned(*)[PSTR])(Ql + 128);   // 128 x 36
    unsigned (*Kl)[PSTR] = Kh + 128;                        // 128 x 36

    const int bh   = blockIdx.y;
    const int row0 = blockIdx.x * 128;
    const int tid  = threadIdx.x;
    const int warp = tid >> 5;
    const int g = (tid >> 2) & 7, tg = tid & 3;
    const int wm0 = warp * 16;

    const float* Qm = g_Q + ((size_t)bh * S_ + row0) * DK_;
    const float* Km = g_K + (size_t)bh * S_ * DK_;

    // Stage whole Q strip (128 x 64), scaled by 1/sqrt(DK), hi/lo split.
    #pragma unroll
    for (int p = 0; p < 8; p++) {
        int lin = tid + (p << 8);          // 0..2047
        int r = lin >> 4, c = (lin & 15) << 2;
        float4 v = *reinterpret_cast<const float4*>(Qm + (size_t)r * DK_ + c);
        v.x *= 0.125f; v.y *= 0.125f; v.z *= 0.125f; v.w *= 0.125f;
        split4(&Qh[r][c], &Ql[r][c], v);
    }

    float m0 = -1e30f, m1 = -1e30f, s0 = 0.f, s1 = 0.f;

    for (int ct = 0; ct < S_ / 128; ct++) {
        const int col0 = ct * 128;
        float acc[16][4] = {};

        #pragma unroll
        for (int dk0 = 0; dk0 < DK_; dk0 += 32) {
            __syncthreads();
            // K chunk: 128 key rows x 32 depth, hi/lo split
            #pragma unroll
            for (int p = 0; p < 4; p++) {
                int lin = tid + (p << 8);
                int r = lin >> 3, c = (lin & 7) << 2;
                float4 v = *reinterpret_cast<const float4*>(Km + (size_t)(col0 + r) * DK_ + dk0 + c);
                split4(&Kh[r][c], &Kl[r][c], v);
            }
            __syncthreads();
            #pragma unroll
            for (int ks = 0; ks < 32; ks += 8) {
                unsigned ah[4], al[4];
                ah[0] = Qh[wm0+g  ][dk0+ks+tg]; ah[1] = Qh[wm0+g+8][dk0+ks+tg];
                ah[2] = Qh[wm0+g  ][dk0+ks+tg+4]; ah[3] = Qh[wm0+g+8][dk0+ks+tg+4];
                al[0] = Ql[wm0+g  ][dk0+ks+tg]; al[1] = Ql[wm0+g+8][dk0+ks+tg];
                al[2] = Ql[wm0+g  ][dk0+ks+tg+4]; al[3] = Ql[wm0+g+8][dk0+ks+tg+4];
                #pragma unroll
                for (int nf = 0; nf < 16; nf++) {
                    int r = nf * 8 + g;
                    unsigned bh0 = Kh[r][ks+tg], bh1 = Kh[r][ks+tg+4];
                    unsigned bl0 = Kl[r][ks+tg], bl1 = Kl[r][ks+tg+4];
                    mma8(acc[nf], ah, bh0, bh1);
                    mma8(acc[nf], ah, bl0, bl1);
                    mma8(acc[nf], al, bh0, bh1);
                }
            }
        }

        // --- online stats for this tile (rows wm0+g and wm0+g+8) ---
        float tm0 = -1e30f, tm1 = -1e30f;
        #pragma unroll
        for (int nf = 0; nf < 16; nf++) {
            tm0 = fmaxf(tm0, fmaxf(acc[nf][0], acc[nf][1]));
            tm1 = fmaxf(tm1, fmaxf(acc[nf][2], acc[nf][3]));
        }
        tm0 = fmaxf(tm0, __shfl_xor_sync(0xffffffffu, tm0, 1));
        tm0 = fmaxf(tm0, __shfl_xor_sync(0xffffffffu, tm0, 2));
        tm1 = fmaxf(tm1, __shfl_xor_sync(0xffffffffu, tm1, 1));
        tm1 = fmaxf(tm1, __shfl_xor_sync(0xffffffffu, tm1, 2));
        float n0 = fmaxf(m0, tm0), n1 = fmaxf(m1, tm1);
        float e0 = 0.f, e1 = 0.f;
        #pragma unroll
        for (int nf = 0; nf < 16; nf++) {
            e0 += __expf(acc[nf][0] - n0) + __expf(acc[nf][1] - n0);
            e1 += __expf(acc[nf][2] - n1) + __expf(acc[nf][3] - n1);
        }
        e0 += __shfl_xor_sync(0xffffffffu, e0, 1);
        e0 += __shfl_xor_sync(0xffffffffu, e0, 2);
        e1 += __shfl_xor_sync(0xffffffffu, e1, 1);
        e1 += __shfl_xor_sync(0xffffffffu, e1, 2);
        s0 = s0 * __expf(m0 - n0) + e0;  m0 = n0;
        s1 = s1 * __expf(m1 - n1) + e1;  m1 = n1;

        // --- write raw scores ---
        int q0 = row0 + wm0 + g;
        #pragma unroll
        for (int nf = 0; nf < 16; nf++) {
            int c0 = col0 + nf * 8 + 2 * tg;
            *reinterpret_cast<float2*>(&attn[((size_t)bh * S_ + q0) * S_ + c0])
                = make_float2(acc[nf][0], acc[nf][1]);
            *reinterpret_cast<float2*>(&attn[((size_t)bh * S_ + q0 + 8) * S_ + c0])
                = make_float2(acc[nf][2], acc[nf][3]);
        }
    }

    if (tg == 0) {
        int q0 = row0 + wm0 + g;
        g_rmax[bh * S_ + q0]     = m0;
        g_rinv[bh * S_ + q0]     = 1.0f / s0;
        g_rmax[bh * S_ + q0 + 8] = m1;
        g_rinv[bh * S_ + q0 + 8] = 1.0f / s1;
    }
}

// ---------------------------------------------------------------------------
// Kernel 3: normalize weights in place AND ctx = P @ V  (1xTF32).
// The fp32 softmax weights written to d_out are exact; tf32 only affects the
// context (output 0) at ~2^-11 relative — within threshold with margin.
// Block: 128 q x 64 dk, loop kcol in 32-chunks. 8 warps (4m x 2n).
// ---------------------------------------------------------------------------
__global__ void __launch_bounds__(256) av_kernel(float* __restrict__ attn)
{
    extern __shared__ unsigned sm[];
    unsigned (*AhS)[PSTR] = (unsigned(*)[PSTR])sm;           // 128*36
    unsigned (*VhS)[VSTR] = (unsigned(*)[VSTR])(AhS + 128);  // 32*72
    float* rmaxS = (float*)(VhS + 32);                       // 128
    float* rinvS = rmaxS + 128;                              // 128

    const int bh   = blockIdx.y;
    const int row0 = blockIdx.x * 128;
    const int tid  = threadIdx.x;
    const int warp = tid >> 5;
    const int g = (tid >> 2) & 7, tg = tid & 3;
    const int wm0 = (warp & 3) * 32, wn0 = (warp >> 2) * 32;

    if (tid < 128) {
        rmaxS[tid] = g_rmax[bh * S_ + row0 + tid];
        rinvS[tid] = g_rinv[bh * S_ + row0 + tid];
    }
    __syncthreads();

    float* Abase = attn + ((size_t)bh * S_ + row0) * S_;
    const float* Vbase = g_V + (size_t)bh * S_ * DK_;

    float acc[2][4][4] = {};

    for (int kb = 0; kb < S_; kb += 32) {
        // scores chunk: read raw, softmax-normalize (fp32, exact output),
        // write back, stage tf32-hi into smem.
        #pragma unroll
        for (int p = 0; p < 4; p++) {
            int lin = tid + (p << 8);
            int r = lin >> 3, c = (lin & 7) << 2;
            float4* gp = reinterpret_cast<float4*>(Abase + (size_t)r * S_ + kb + c);
            float4 v = *gp;
            float m = rmaxS[r], inv = rinvS[r];
            v.x = __expf(v.x - m) * inv;
            v.y = __expf(v.y - m) * inv;
            v.z = __expf(v.z - m) * inv;
            v.w = __expf(v.w - m) * inv;
            *gp = v;
            cvt4(&AhS[r][c], v);
        }
        // V chunk: 32 kcol-rows x 64 dk, stored [k][n]
        #pragma unroll
        for (int p = 0; p < 2; p++) {
            int lin = tid + (p << 8);
            int r = lin >> 4, c = (lin & 15) << 2;
            float4 v = *reinterpret_cast<const float4*>(Vbase + (size_t)(kb + r) * DK_ + c);
            cvt4(&VhS[r][c], v);
        }
        __syncthreads();
        #pragma unroll
        for (int ks = 0; ks < 32; ks += 8) {
            unsigned ah[2][4];
            #pragma unroll
            for (int mf = 0; mf < 2; mf++) {
                int r = wm0 + mf * 16;
                ah[mf][0] = AhS[r+g  ][ks+tg]; ah[mf][1] = AhS[r+g+8][ks+tg];
                ah[mf][2] = AhS[r+g  ][ks+tg+4]; ah[mf][3] = AhS[r+g+8][ks+tg+4];
            }
            #pragma unroll
            for (int nf = 0; nf < 4; nf++) {
                int vn = wn0 + nf * 8 + g;
                unsigned bh0 = VhS[ks+tg][vn], bh1 = VhS[ks+tg+4][vn];
                #pragma unroll
                for (int mf = 0; mf < 2; mf++)
                    mma8(acc[mf][nf], ah[mf], bh0, bh1);
            }
        }
        __syncthreads();
    }

    // Epilogue: merged-head context  g_ctx[(b*S+q)*D + h*DK + c]
    const int b = bh >> 4, h = bh & (H_ - 1);
    #pragma unroll
    for (int nf = 0; nf < 4; nf++) {
        int c0 = wn0 + nf * 8 + 2 * tg;
        #pragma unroll
        for (int mf = 0; mf < 2; mf++) {
            int q = row0 + wm0 + mf * 16 + g;
            float2 o0 = make_float2(acc[mf][nf][0], acc[mf][nf][1]);
            float2 o1 = make_float2(acc[mf][nf][2], acc[mf][nf][3]);
            *reinterpret_cast<float2*>(&g_ctx[((size_t)(b * S_ + q))     * D_ + h * DK_ + c0]) = o0;
            *reinterpret_cast<float2*>(&g_ctx[((size_t)(b * S_ + q + 8)) * D_ + h * DK_ + c0]) = o1;
        }
    }
}

// ---------------------------------------------------------------------------
// Kernel 4: output projection out = ctx @ W_o^T + b_o  (3xTF32)
// ---------------------------------------------------------------------------
__global__ void __launch_bounds__(256) outproj_kernel(
    const float* __restrict__ Wo, const float* __restrict__ bo, float* __restrict__ out)
{
    extern __shared__ unsigned sm[];
    unsigned (*Ah)[PSTR] = (unsigned(*)[PSTR])sm;
    unsigned (*Al)[PSTR] = Ah + 128;
    unsigned (*Bh)[PSTR] = Al + 128;
    unsigned (*Bl)[PSTR] = Bh + 128;

    const int tid = threadIdx.x;
    const int warp = tid >> 5;
    const int g = (tid >> 2) & 7, tg = tid & 3;
    const int wm0 = (warp & 1) * 64, wn0 = (warp >> 1) * 32;
    const int row0 = blockIdx.y * 128;
    const int col0 = blockIdx.x * 128;

    float acc[4][4][4] = {};

    for (int kb = 0; kb < D_; kb += 32) {
        #pragma unroll
        for (int p = 0; p < 4; p++) {
            int lin = tid + (p << 8);
            int r = lin >> 3, c = (lin & 7) << 2;
            float4 v = *reinterpret_cast<const float4*>(g_ctx + (size_t)(row0 + r) * D_ + kb + c);
            split4(&Ah[r][c], &Al[r][c], v);
        }
        #pragma unroll
        for (int p = 0; p < 4; p++) {
            int lin = tid + (p << 8);
            int r = lin >> 3, c = (lin & 7) << 2;
            float4 v = *reinterpret_cast<const float4*>(Wo + (size_t)(col0 + r) * D_ + kb + c);
            split4(&Bh[r][c], &Bl[r][c], v);
        }
        __syncthreads();
        #pragma unroll
        for (int ks = 0; ks < 32; ks += 8) {
            unsigned ah[4][4], al[4][4];
            #pragma unroll
            for (int mf = 0; mf < 4; mf++) {
                int r = wm0 + mf * 16;
                ah[mf][0] = Ah[r+g  ][ks+tg]; ah[mf][1] = Ah[r+g+8][ks+tg];
                ah[mf][2] = Ah[r+g  ][ks+tg+4]; ah[mf][3] = Ah[r+g+8][ks+tg+4];
                al[mf][0] = Al[r+g  ][ks+tg]; al[mf][1] = Al[r+g+8][ks+tg];
                al[mf][2] = Al[r+g  ][ks+tg+4]; al[mf][3] = Al[r+g+8][ks+tg+4];
            }
            #pragma unroll
            for (int nf = 0; nf < 4; nf++) {
                int r = wn0 + nf * 8 + g;
                unsigned bh0 = Bh[r][ks+tg], bh1 = Bh[r][ks+tg+4];
                unsigned bl0 = Bl[r][ks+tg], bl1 = Bl[r][ks+tg+4];
                #pragma unroll
                for (int mf = 0; mf < 4; mf++) {
                    mma8(acc[mf][nf], ah[mf], bh0, bh1);
                    mma8(acc[mf][nf], ah[mf], bl0, bl1);
                    mma8(acc[mf][nf], al[mf], bh0, bh1);
                }
            }
        }
        __syncthreads();
    }

    #pragma unroll
    for (int nf = 0; nf < 4; nf++) {
        int n0 = col0 + wn0 + nf * 8 + 2 * tg;
        float b0v = bo[n0], b1v = bo[n0 + 1];
        #pragma unroll
        for (int mf = 0; mf < 4; mf++) {
            int m = row0 + wm0 + mf * 16 + g;
            float2 o0 = make_float2(acc[mf][nf][0] + b0v, acc[mf][nf][1] + b1v);
            float2 o1 = make_float2(acc[mf][nf][2] + b0v, acc[mf][nf][3] + b1v);
            *reinterpret_cast<float2*>(&out[(size_t)m * D_ + n0])       = o0;
            *reinterpret_cast<float2*>(&out[(size_t)(m + 8) * D_ + n0]) = o1;
        }
    }
}

// ---------------------------------------------------------------------------
extern "C" void kernel_launch(void* const* d_in, const int* in_sizes, int n_in,
                              void* d_out, int out_size)
{
    const float* query = (const float*)d_in[0];
    const float* key_  = (const float*)d_in[1];
    const float* value = (const float*)d_in[2];
    const float* W_q = (const float*)d_in[3];
    const float* b_q = (const float*)d_in[4];
    const float* W_k = (const float*)d_in[5];
    const float* b_k = (const float*)d_in[6];
    const float* W_v = (const float*)d_in[7];
    const float* b_v = (const float*)d_in[8];
    const float* W_o = (const float*)d_in[9];
    const float* b_o = (const float*)d_in[10];

    float* out  = (float*)d_out;                       // [B,S,D]
    float* attn = out + (size_t)B_ * S_ * D_;          // [B,H,S,S]

    const int DSMEM  = 4 * 128 * PSTR * sizeof(unsigned);                        // 73728 B
    const int SCSMEM = (2 * 128 * QSTR + 2 * 128 * PSTR) * sizeof(unsigned);     // 106496 B
    const int AVSMEM = (128 * PSTR + 32 * VSTR) * sizeof(unsigned)
                     + 2 * 128 * sizeof(float);                                  // 28672 B
    cudaFuncSetAttribute(proj_kernel,    cudaFuncAttributeMaxDynamicSharedMemorySize, DSMEM);
    cudaFuncSetAttribute(scores_kernel,  cudaFuncAttributeMaxDynamicSharedMemorySize, SCSMEM);
    cudaFuncSetAttribute(av_kernel,      cudaFuncAttributeMaxDynamicSharedMemorySize, AVSMEM);
    cudaFuncSetAttribute(outproj_kernel, cudaFuncAttributeMaxDynamicSharedMemorySize, DSMEM);

    proj_kernel<<<dim3(D_/128, NROWS/128, 3), 256, DSMEM>>>(
        query, key_, value, W_q, b_q, W_k, b_k, W_v, b_v);

    scores_kernel<<<dim3(S_/128, NBH), 256, SCSMEM>>>(attn);

    av_kernel<<<dim3(S_/128, NBH), 256, AVSMEM>>>(attn);

    outproj_kernel<<<dim3(D_/128, NROWS/128), 256, DSMEM>>>(W_o, b_o, out);
}

// round 7
// speedup vs baseline: 1.6595x; 1.2883x over previous
#include <cuda_runtime.h>
#include <math.h>

#define B_ 2
#define S_ 2048
#define D_ 1024
#define H_ 16
#define DK_ 64
#define NROWS (B_*S_)      // 4096
#define NBH (B_*H_)        // 32

// Scratch (allocation-free): module-load static device memory
__device__ float g_Q[NBH*S_*DK_];   // [b,h,s,dk]
__device__ float g_K[NBH*S_*DK_];
__device__ float g_V[NBH*S_*DK_];
__device__ float g_ctx[(size_t)NROWS*D_];
__device__ float g_rmax[NBH*S_];
__device__ float g_rinv[NBH*S_];

// ---------------------------------------------------------------------------
// tf32 helpers
// ---------------------------------------------------------------------------
__device__ __forceinline__ unsigned cvt_tf32(float f) {
    unsigned u; asm("cvt.rna.tf32.f32 %0, %1;" : "=r"(u) : "f"(f)); return u;
}
__device__ __forceinline__ void split1(float f, unsigned &h, unsigned &l) {
    h = cvt_tf32(f);
    l = cvt_tf32(f - __uint_as_float(h));
}
__device__ __forceinline__ void split4(unsigned* h, unsigned* l, float4 v) {
    split1(v.x, h[0], l[0]); split1(v.y, h[1], l[1]);
    split1(v.z, h[2], l[2]); split1(v.w, h[3], l[3]);
}
__device__ __forceinline__ void cvt4(unsigned* h, float4 v) {
    h[0] = cvt_tf32(v.x); h[1] = cvt_tf32(v.y);
    h[2] = cvt_tf32(v.z); h[3] = cvt_tf32(v.w);
}
// m16n8k8 tf32 mma, accumulate into c[4]
__device__ __forceinline__ void mma8(float* c, const unsigned* a, unsigned b0, unsigned b1) {
    asm volatile(
        "mma.sync.aligned.m16n8k8.row.col.f32.tf32.tf32.f32 "
        "{%0,%1,%2,%3},{%4,%5,%6,%7},{%8,%9},{%0,%1,%2,%3};\n"
        : "+f"(c[0]), "+f"(c[1]), "+f"(c[2]), "+f"(c[3])
        : "r"(a[0]), "r"(a[1]), "r"(a[2]), "r"(a[3]), "r"(b0), "r"(b1));
}

#define PSTR 36   // smem row stride (u32) for [row][k<=32] tiles (36%32=4 -> 4g+tg distinct)
#define QSTR 68   // smem row stride for [row][64] Q tiles (68%32=4)
#define VSTR 72   // smem row stride for V [k][64 n] tiles (72%32=8 -> 8tg+g distinct)

// ---------------------------------------------------------------------------
// Kernel 1: QKV projections (3xTF32) with register prefetch double-buffering.
// ---------------------------------------------------------------------------
__global__ void __launch_bounds__(256) proj_kernel(
    const float* __restrict__ Xq, const float* __restrict__ Xk, const float* __restrict__ Xv,
    const float* __restrict__ Wq, const float* __restrict__ bq,
    const float* __restrict__ Wk, const float* __restrict__ bk,
    const float* __restrict__ Wv, const float* __restrict__ bv)
{
    const int which = blockIdx.z;
    const float* X    = (which == 0) ? Xq : (which == 1) ? Xk : Xv;
    const float* W    = (which == 0) ? Wq : (which == 1) ? Wk : Wv;
    const float* bias = (which == 0) ? bq : (which == 1) ? bk : bv;
    float* Out        = (which == 0) ? g_Q : (which == 1) ? g_K : g_V;

    extern __shared__ unsigned sm[];
    unsigned (*Ah)[PSTR] = (unsigned(*)[PSTR])sm;
    unsigned (*Al)[PSTR] = Ah + 128;
    unsigned (*Bh)[PSTR] = Al + 128;
    unsigned (*Bl)[PSTR] = Bh + 128;

    const int tid = threadIdx.x;
    const int warp = tid >> 5;
    const int g = (tid >> 2) & 7, tg = tid & 3;
    const int wm0 = (warp & 1) * 64, wn0 = (warp >> 1) * 32;
    const int row0 = blockIdx.y * 128;
    const int col0 = blockIdx.x * 128;
    const int lr = tid >> 3, lc = (tid & 7) << 2;   // loader row/col (covers 32 rows per 256 thds)

    float acc[4][4][4] = {};
    float4 pa[4], pb[4];

    // prologue prefetch (kb = 0)
    #pragma unroll
    for (int p = 0; p < 4; p++) {
        pa[p] = *reinterpret_cast<const float4*>(X + (size_t)(row0 + lr + p * 32) * D_ + lc);
        pb[p] = *reinterpret_cast<const float4*>(W + (size_t)(col0 + lr + p * 32) * D_ + lc);
    }

    for (int kb = 0; kb < D_; kb += 32) {
        // store current chunk (split) to smem
        #pragma unroll
        for (int p = 0; p < 4; p++) {
            split4(&Ah[lr + p * 32][lc], &Al[lr + p * 32][lc], pa[p]);
            split4(&Bh[lr + p * 32][lc], &Bl[lr + p * 32][lc], pb[p]);
        }
        __syncthreads();
        // prefetch next chunk (latency hidden under MMA phase)
        if (kb + 32 < D_) {
            #pragma unroll
            for (int p = 0; p < 4; p++) {
                pa[p] = *reinterpret_cast<const float4*>(X + (size_t)(row0 + lr + p * 32) * D_ + kb + 32 + lc);
                pb[p] = *reinterpret_cast<const float4*>(W + (size_t)(col0 + lr + p * 32) * D_ + kb + 32 + lc);
            }
        }
        #pragma unroll
        for (int ks = 0; ks < 32; ks += 8) {
            unsigned ah[4][4], al[4][4];
            #pragma unroll
            for (int mf = 0; mf < 4; mf++) {
                int r = wm0 + mf * 16;
                ah[mf][0] = Ah[r+g  ][ks+tg]; ah[mf][1] = Ah[r+g+8][ks+tg];
                ah[mf][2] = Ah[r+g  ][ks+tg+4]; ah[mf][3] = Ah[r+g+8][ks+tg+4];
                al[mf][0] = Al[r+g  ][ks+tg]; al[mf][1] = Al[r+g+8][ks+tg];
                al[mf][2] = Al[r+g  ][ks+tg+4]; al[mf][3] = Al[r+g+8][ks+tg+4];
            }
            #pragma unroll
            for (int nf = 0; nf < 4; nf++) {
                int r = wn0 + nf * 8 + g;
                unsigned bh0 = Bh[r][ks+tg], bh1 = Bh[r][ks+tg+4];
                unsigned bl0 = Bl[r][ks+tg], bl1 = Bl[r][ks+tg+4];
                #pragma unroll
                for (int mf = 0; mf < 4; mf++) {
                    mma8(acc[mf][nf], ah[mf], bh0, bh1);
                    mma8(acc[mf][nf], ah[mf], bl0, bl1);
                    mma8(acc[mf][nf], al[mf], bh0, bh1);
                }
            }
        }
        __syncthreads();
    }

    // Epilogue: bias + split-head store Out[((b*H+h)*S+s)*DK+dk]
    #pragma unroll
    for (int nf = 0; nf < 4; nf++) {
        int n0 = col0 + wn0 + nf * 8 + 2 * tg;
        float b0v = bias[n0], b1v = bias[n0 + 1];
        int h = n0 >> 6, dk = n0 & (DK_ - 1);
        #pragma unroll
        for (int mf = 0; mf < 4; mf++) {
            int m = row0 + wm0 + mf * 16 + g;
            int b = m >> 11, s = m & (S_ - 1);
            size_t base = (((size_t)(b * H_ + h)) * S_) * DK_ + dk;
            float2 o0 = make_float2(acc[mf][nf][0] + b0v, acc[mf][nf][1] + b1v);
            float2 o1 = make_float2(acc[mf][nf][2] + b0v, acc[mf][nf][3] + b1v);
            *reinterpret_cast<float2*>(&Out[base + (size_t)s * DK_])       = o0;
            *reinterpret_cast<float2*>(&Out[base + (size_t)(s + 8) * DK_]) = o1;
        }
    }
}

// ---------------------------------------------------------------------------
// Kernel 2: scores = (Q*scale) @ K^T (3xTF32) + fused online softmax stats,
// with register prefetch of K chunks.
// ---------------------------------------------------------------------------
__global__ void __launch_bounds__(256) scores_kernel(float* __restrict__ attn)
{
    extern __shared__ unsigned sm[];
    unsigned (*Qh)[QSTR] = (unsigned(*)[QSTR])sm;           // 128 x 68
    unsigned (*Ql)[QSTR] = Qh + 128;                        // 128 x 68
    unsigned (*Kh)[PSTR] = (unsigned(*)[PSTR])(Ql + 128);   // 128 x 36
    unsigned (*Kl)[PSTR] = Kh + 128;                        // 128 x 36

    const int bh   = blockIdx.y;
    const int row0 = blockIdx.x * 128;
    const int tid  = threadIdx.x;
    const int warp = tid >> 5;
    const int g = (tid >> 2) & 7, tg = tid & 3;
    const int wm0 = warp * 16;
    const int lr = tid >> 3, lc = (tid & 7) << 2;
    const int NT = S_ / 128;

    const float* Qm = g_Q + ((size_t)bh * S_ + row0) * DK_;
    const float* Km = g_K + (size_t)bh * S_ * DK_;

    // Stage whole Q strip (128 x 64), scaled, hi/lo split.
    #pragma unroll
    for (int p = 0; p < 8; p++) {
        int lin = tid + (p << 8);
        int r = lin >> 4, c = (lin & 15) << 2;
        float4 v = *reinterpret_cast<const float4*>(Qm + (size_t)r * DK_ + c);
        v.x *= 0.125f; v.y *= 0.125f; v.z *= 0.125f; v.w *= 0.125f;
        split4(&Qh[r][c], &Ql[r][c], v);
    }

    float4 pk[4];
    #pragma unroll
    for (int p = 0; p < 4; p++)
        pk[p] = *reinterpret_cast<const float4*>(Km + (size_t)(lr + p * 32) * DK_ + lc);

    float m0 = -1e30f, m1 = -1e30f, s0 = 0.f, s1 = 0.f;

    for (int ct = 0; ct < NT; ct++) {
        const int col0 = ct * 128;
        float acc[16][4] = {};

        #pragma unroll
        for (int half = 0; half < 2; half++) {
            const int dk0 = half * 32;
            __syncthreads();
            #pragma unroll
            for (int p = 0; p < 4; p++)
                split4(&Kh[lr + p * 32][lc], &Kl[lr + p * 32][lc], pk[p]);
            __syncthreads();
            // prefetch next K chunk
            {
                int nct = half ? ct + 1 : ct;
                int ndk = half ? 0 : 32;
                if (nct < NT) {
                    #pragma unroll
                    for (int p = 0; p < 4; p++)
                        pk[p] = *reinterpret_cast<const float4*>(
                            Km + (size_t)(nct * 128 + lr + p * 32) * DK_ + ndk + lc);
                }
            }
            #pragma unroll
            for (int ks = 0; ks < 32; ks += 8) {
                unsigned ah[4], al[4];
                ah[0] = Qh[wm0+g  ][dk0+ks+tg]; ah[1] = Qh[wm0+g+8][dk0+ks+tg];
                ah[2] = Qh[wm0+g  ][dk0+ks+tg+4]; ah[3] = Qh[wm0+g+8][dk0+ks+tg+4];
                al[0] = Ql[wm0+g  ][dk0+ks+tg]; al[1] = Ql[wm0+g+8][dk0+ks+tg];
                al[2] = Ql[wm0+g  ][dk0+ks+tg+4]; al[3] = Ql[wm0+g+8][dk0+ks+tg+4];
                #pragma unroll
                for (int nf = 0; nf < 16; nf++) {
                    int r = nf * 8 + g;
                    unsigned bh0 = Kh[r][ks+tg], bh1 = Kh[r][ks+tg+4];
                    unsigned bl0 = Kl[r][ks+tg], bl1 = Kl[r][ks+tg+4];
                    mma8(acc[nf], ah, bh0, bh1);
                    mma8(acc[nf], ah, bl0, bl1);
                    mma8(acc[nf], al, bh0, bh1);
                }
            }
        }

        // --- online stats for rows wm0+g and wm0+g+8 ---
        float tm0 = -1e30f, tm1 = -1e30f;
        #pragma unroll
        for (int nf = 0; nf < 16; nf++) {
            tm0 = fmaxf(tm0, fmaxf(acc[nf][0], acc[nf][1]));
            tm1 = fmaxf(tm1, fmaxf(acc[nf][2], acc[nf][3]));
        }
        tm0 = fmaxf(tm0, __shfl_xor_sync(0xffffffffu, tm0, 1));
        tm0 = fmaxf(tm0, __shfl_xor_sync(0xffffffffu, tm0, 2));
        tm1 = fmaxf(tm1, __shfl_xor_sync(0xffffffffu, tm1, 1));
        tm1 = fmaxf(tm1, __shfl_xor_sync(0xffffffffu, tm1, 2));
        float n0 = fmaxf(m0, tm0), n1 = fmaxf(m1, tm1);
        float e0 = 0.f, e1 = 0.f;
        #pragma unroll
        for (int nf = 0; nf < 16; nf++) {
            e0 += __expf(acc[nf][0] - n0) + __expf(acc[nf][1] - n0);
            e1 += __expf(acc[nf][2] - n1) + __expf(acc[nf][3] - n1);
        }
        e0 += __shfl_xor_sync(0xffffffffu, e0, 1);
        e0 += __shfl_xor_sync(0xffffffffu, e0, 2);
        e1 += __shfl_xor_sync(0xffffffffu, e1, 1);
        e1 += __shfl_xor_sync(0xffffffffu, e1, 2);
        s0 = s0 * __expf(m0 - n0) + e0;  m0 = n0;
        s1 = s1 * __expf(m1 - n1) + e1;  m1 = n1;

        // --- write raw scores ---
        int q0 = row0 + wm0 + g;
        #pragma unroll
        for (int nf = 0; nf < 16; nf++) {
            int c0 = col0 + nf * 8 + 2 * tg;
            *reinterpret_cast<float2*>(&attn[((size_t)bh * S_ + q0) * S_ + c0])
                = make_float2(acc[nf][0], acc[nf][1]);
            *reinterpret_cast<float2*>(&attn[((size_t)bh * S_ + q0 + 8) * S_ + c0])
                = make_float2(acc[nf][2], acc[nf][3]);
        }
    }

    if (tg == 0) {
        int q0 = row0 + wm0 + g;
        g_rmax[bh * S_ + q0]     = m0;
        g_rinv[bh * S_ + q0]     = 1.0f / s0;
        g_rmax[bh * S_ + q0 + 8] = m1;
        g_rinv[bh * S_ + q0 + 8] = 1.0f / s1;
    }
}

// ---------------------------------------------------------------------------
// Kernel 3: normalize weights in place AND ctx = P @ V (1xTF32),
// with register prefetch of the attn chunk and V chunk.
// ---------------------------------------------------------------------------
__global__ void __launch_bounds__(256) av_kernel(float* __restrict__ attn)
{
    extern __shared__ unsigned sm[];
    unsigned (*AhS)[PSTR] = (unsigned(*)[PSTR])sm;           // 128*36
    unsigned (*VhS)[VSTR] = (unsigned(*)[VSTR])(AhS + 128);  // 32*72
    float* rmaxS = (float*)(VhS + 32);                       // 128
    float* rinvS = rmaxS + 128;                              // 128

    const int bh   = blockIdx.y;
    const int row0 = blockIdx.x * 128;
    const int tid  = threadIdx.x;
    const int warp = tid >> 5;
    const int g = (tid >> 2) & 7, tg = tid & 3;
    const int wm0 = (warp & 3) * 32, wn0 = (warp >> 2) * 32;
    const int lr = tid >> 3, lc = (tid & 7) << 2;   // attn loader: 32 rows per pass
    const int vr = tid >> 4, vc = (tid & 15) << 2;  // V loader: 16 rows per pass

    if (tid < 128) {
        rmaxS[tid] = g_rmax[bh * S_ + row0 + tid];
        rinvS[tid] = g_rinv[bh * S_ + row0 + tid];
    }

    float* Abase = attn + ((size_t)bh * S_ + row0) * S_;
    const float* Vbase = g_V + (size_t)bh * S_ * DK_;

    float acc[2][4][4] = {};
    float4 pa[4], pv[2];

    #pragma unroll
    for (int p = 0; p < 4; p++)
        pa[p] = *reinterpret_cast<float4*>(Abase + (size_t)(lr + p * 32) * S_ + lc);
    #pragma unroll
    for (int p = 0; p < 2; p++)
        pv[p] = *reinterpret_cast<const float4*>(Vbase + (size_t)(vr + p * 16) * DK_ + vc);
    __syncthreads();   // rmaxS/rinvS ready

    for (int kb = 0; kb < S_; kb += 32) {
        // exp-normalize current chunk, write final weights, stage tf32 smem
        #pragma unroll
        for (int p = 0; p < 4; p++) {
            int r = lr + p * 32;
            float m = rmaxS[r], inv = rinvS[r];
            float4 v = pa[p];
            v.x = __expf(v.x - m) * inv;
            v.y = __expf(v.y - m) * inv;
            v.z = __expf(v.z - m) * inv;
            v.w = __expf(v.w - m) * inv;
            *reinterpret_cast<float4*>(Abase + (size_t)r * S_ + kb + lc) = v;
            cvt4(&AhS[r][lc], v);
        }
        #pragma unroll
        for (int p = 0; p < 2; p++)
            cvt4(&VhS[vr + p * 16][vc], pv[p]);
        __syncthreads();
        // prefetch next chunks
        if (kb + 32 < S_) {
            #pragma unroll
            for (int p = 0; p < 4; p++)
                pa[p] = *reinterpret_cast<float4*>(Abase + (size_t)(lr + p * 32) * S_ + kb + 32 + lc);
            #pragma unroll
            for (int p = 0; p < 2; p++)
                pv[p] = *reinterpret_cast<const float4*>(Vbase + (size_t)(kb + 32 + vr + p * 16) * DK_ + vc);
        }
        #pragma unroll
        for (int ks = 0; ks < 32; ks += 8) {
            unsigned ah[2][4];
            #pragma unroll
            for (int mf = 0; mf < 2; mf++) {
                int r = wm0 + mf * 16;
                ah[mf][0] = AhS[r+g  ][ks+tg]; ah[mf][1] = AhS[r+g+8][ks+tg];
                ah[mf][2] = AhS[r+g  ][ks+tg+4]; ah[mf][3] = AhS[r+g+8][ks+tg+4];
            }
            #pragma unroll
            for (int nf = 0; nf < 4; nf++) {
                int vn = wn0 + nf * 8 + g;
                unsigned bh0 = VhS[ks+tg][vn], bh1 = VhS[ks+tg+4][vn];
                #pragma unroll
                for (int mf = 0; mf < 2; mf++)
                    mma8(acc[mf][nf], ah[mf], bh0, bh1);
            }
        }
        __syncthreads();
    }

    // Epilogue: merged-head context
    const int b = bh >> 4, h = bh & (H_ - 1);
    #pragma unroll
    for (int nf = 0; nf < 4; nf++) {
        int c0 = wn0 + nf * 8 + 2 * tg;
        #pragma unroll
        for (int mf = 0; mf < 2; mf++) {
            int q = row0 + wm0 + mf * 16 + g;
            float2 o0 = make_float2(acc[mf][nf][0], acc[mf][nf][1]);
            float2 o1 = make_float2(acc[mf][nf][2], acc[mf][nf][3]);
            *reinterpret_cast<float2*>(&g_ctx[((size_t)(b * S_ + q))     * D_ + h * DK_ + c0]) = o0;
            *reinterpret_cast<float2*>(&g_ctx[((size_t)(b * S_ + q + 8)) * D_ + h * DK_ + c0]) = o1;
        }
    }
}

// ---------------------------------------------------------------------------
// Kernel 4: output projection out = ctx @ W_o^T + b_o  (3xTF32), prefetched.
// ---------------------------------------------------------------------------
__global__ void __launch_bounds__(256) outproj_kernel(
    const float* __restrict__ Wo, const float* __restrict__ bo, float* __restrict__ out)
{
    extern __shared__ unsigned sm[];
    unsigned (*Ah)[PSTR] = (unsigned(*)[PSTR])sm;
    unsigned (*Al)[PSTR] = Ah + 128;
    unsigned (*Bh)[PSTR] = Al + 128;
    unsigned (*Bl)[PSTR] = Bh + 128;

    const int tid = threadIdx.x;
    const int warp = tid >> 5;
    const int g = (tid >> 2) & 7, tg = tid & 3;
    const int wm0 = (warp & 1) * 64, wn0 = (warp >> 1) * 32;
    const int row0 = blockIdx.y * 128;
    const int col0 = blockIdx.x * 128;
    const int lr = tid >> 3, lc = (tid & 7) << 2;

    float acc[4][4][4] = {};
    float4 pa[4], pb[4];

    #pragma unroll
    for (int p = 0; p < 4; p++) {
        pa[p] = *reinterpret_cast<const float4*>(g_ctx + (size_t)(row0 + lr + p * 32) * D_ + lc);
        pb[p] = *reinterpret_cast<const float4*>(Wo + (size_t)(col0 + lr + p * 32) * D_ + lc);
    }

    for (int kb = 0; kb < D_; kb += 32) {
        #pragma unroll
        for (int p = 0; p < 4; p++) {
            split4(&Ah[lr + p * 32][lc], &Al[lr + p * 32][lc], pa[p]);
            split4(&Bh[lr + p * 32][lc], &Bl[lr + p * 32][lc], pb[p]);
        }
        __syncthreads();
        if (kb + 32 < D_) {
            #pragma unroll
            for (int p = 0; p < 4; p++) {
                pa[p] = *reinterpret_cast<const float4*>(g_ctx + (size_t)(row0 + lr + p * 32) * D_ + kb + 32 + lc);
                pb[p] = *reinterpret_cast<const float4*>(Wo + (size_t)(col0 + lr + p * 32) * D_ + kb + 32 + lc);
            }
        }
        #pragma unroll
        for (int ks = 0; ks < 32; ks += 8) {
            unsigned ah[4][4], al[4][4];
            #pragma unroll
            for (int mf = 0; mf < 4; mf++) {
                int r = wm0 + mf * 16;
                ah[mf][0] = Ah[r+g  ][ks+tg]; ah[mf][1] = Ah[r+g+8][ks+tg];
                ah[mf][2] = Ah[r+g  ][ks+tg+4]; ah[mf][3] = Ah[r+g+8][ks+tg+4];
                al[mf][0] = Al[r+g  ][ks+tg]; al[mf][1] = Al[r+g+8][ks+tg];
                al[mf][2] = Al[r+g  ][ks+tg+4]; al[mf][3] = Al[r+g+8][ks+tg+4];
            }
            #pragma unroll
            for (int nf = 0; nf < 4; nf++) {
                int r = wn0 + nf * 8 + g;
                unsigned bh0 = Bh[r][ks+tg], bh1 = Bh[r][ks+tg+4];
                unsigned bl0 = Bl[r][ks+tg], bl1 = Bl[r][ks+tg+4];
                #pragma unroll
                for (int mf = 0; mf < 4; mf++) {
                    mma8(acc[mf][nf], ah[mf], bh0, bh1);
                    mma8(acc[mf][nf], ah[mf], bl0, bl1);
                    mma8(acc[mf][nf], al[mf], bh0, bh1);
                }
            }
        }
        __syncthreads();
    }

    #pragma unroll
    for (int nf = 0; nf < 4; nf++) {
        int n0 = col0 + wn0 + nf * 8 + 2 * tg;
        float b0v = bo[n0], b1v = bo[n0 + 1];
        #pragma unroll
        for (int mf = 0; mf < 4; mf++) {
            int m = row0 + wm0 + mf * 16 + g;
            float2 o0 = make_float2(acc[mf][nf][0] + b0v, acc[mf][nf][1] + b1v);
            float2 o1 = make_float2(acc[mf][nf][2] + b0v, acc[mf][nf][3] + b1v);
            *reinterpret_cast<float2*>(&out[(size_t)m * D_ + n0])       = o0;
            *reinterpret_cast<float2*>(&out[(size_t)(m + 8) * D_ + n0]) = o1;
        }
    }
}

// ---------------------------------------------------------------------------
extern "C" void kernel_launch(void* const* d_in, const int* in_sizes, int n_in,
                              void* d_out, int out_size)
{
    const float* query = (const float*)d_in[0];
    const float* key_  = (const float*)d_in[1];
    const float* value = (const float*)d_in[2];
    const float* W_q = (const float*)d_in[3];
    const float* b_q = (const float*)d_in[4];
    const float* W_k = (const float*)d_in[5];
    const float* b_k = (const float*)d_in[6];
    const float* W_v = (const float*)d_in[7];
    const float* b_v = (const float*)d_in[8];
    const float* W_o = (const float*)d_in[9];
    const float* b_o = (const float*)d_in[10];

    float* out  = (float*)d_out;                       // [B,S,D]
    float* attn = out + (size_t)B_ * S_ * D_;          // [B,H,S,S]

    const int DSMEM  = 4 * 128 * PSTR * sizeof(unsigned);                        // 73728 B
    const int SCSMEM = (2 * 128 * QSTR + 2 * 128 * PSTR) * sizeof(unsigned);     // 106496 B
    const int AVSMEM = (128 * PSTR + 32 * VSTR) * sizeof(unsigned)
                     + 2 * 128 * sizeof(float);                                  // 28672 B
    cudaFuncSetAttribute(proj_kernel,    cudaFuncAttributeMaxDynamicSharedMemorySize, DSMEM);
    cudaFuncSetAttribute(scores_kernel,  cudaFuncAttributeMaxDynamicSharedMemorySize, SCSMEM);
    cudaFuncSetAttribute(av_kernel,      cudaFuncAttributeMaxDynamicSharedMemorySize, AVSMEM);
    cudaFuncSetAttribute(outproj_kernel, cudaFuncAttributeMaxDynamicSharedMemorySize, DSMEM);

    proj_kernel<<<dim3(D_/128, NROWS/128, 3), 256, DSMEM>>>(
        query, key_, value, W_q, b_q, W_k, b_k, W_v, b_v);

    scores_kernel<<<dim3(S_/128, NBH), 256, SCSMEM>>>(attn);

    av_kernel<<<dim3(S_/128, NBH), 256, AVSMEM>>>(attn);

    outproj_kernel<<<dim3(D_/128, NROWS/128), 256, DSMEM>>>(W_o, b_o, out);
}